// round 6
// baseline (speedup 1.0000x reference)
#include <cuda_runtime.h>
#include <cstdint>

// Haar DWT2: in [B=8, C=32, H=512, W=512] f32 -> out [B, 4, C, 256, 256] f32
// Subband order: LL, LH, HL, HH (pywt dwt2 'haar').
//
// Best-explored config: 4 rows x 4 cols per thread (4x LDG.128, each warp
// instruction fully contiguous 512B, front-batched), 2 rows x 2 cols per
// subband out (8x STG.64, contiguous 256B per warp instruction).
// Pure 32-bit indexing (all offsets < 2^27 elements).

#define B_  8
#define C_  32
#define H_  512
#define W_  512
#define H2 (H_/2)
#define W2 (W_/2)

__global__ void __launch_bounds__(256) haar_dwt2_kernel(
    const float* __restrict__ in, float* __restrict__ out)
{
    // total threads = B*C*(H2/2)*(W2/2) = 8*32*128*128 = 4,194,304
    const unsigned tid = blockIdx.x * 256u + threadIdx.x;

    const unsigned wpair = tid & (W2/2 - 1);            // 0..127 (2 output cols)
    const unsigned hq    = (tid >> 7) & (H2/2 - 1);     // 0..127 (2 output rows)
    const unsigned bc    = tid >> 14;                   // 0..255 (b*32 + c)
    const unsigned b     = bc >> 5;
    const unsigned c     = bc & 31;

    // Input: rows 4*hq .. 4*hq+3, cols 4*wpair .. 4*wpair+3
    const unsigned in_base = (bc * H_ + 4u * hq) * W_ + 4u * wpair;
    const float4 r0 = *reinterpret_cast<const float4*>(in + in_base);
    const float4 r1 = *reinterpret_cast<const float4*>(in + in_base + W_);
    const float4 r2 = *reinterpret_cast<const float4*>(in + in_base + 2u * W_);
    const float4 r3 = *reinterpret_cast<const float4*>(in + in_base + 3u * W_);

    // Output row 0 (h2 = 2*hq): from r0/r1
    float2 LL0, LH0, HL0, HH0;
    LL0.x = (r0.x + r0.y + r1.x + r1.y) * 0.5f;
    LH0.x = (r0.x + r0.y - r1.x - r1.y) * 0.5f;
    HL0.x = (r0.x - r0.y + r1.x - r1.y) * 0.5f;
    HH0.x = (r0.x - r0.y - r1.x + r1.y) * 0.5f;
    LL0.y = (r0.z + r0.w + r1.z + r1.w) * 0.5f;
    LH0.y = (r0.z + r0.w - r1.z - r1.w) * 0.5f;
    HL0.y = (r0.z - r0.w + r1.z - r1.w) * 0.5f;
    HH0.y = (r0.z - r0.w - r1.z + r1.w) * 0.5f;

    // Output row 1 (h2 = 2*hq+1): from r2/r3
    float2 LL1, LH1, HL1, HH1;
    LL1.x = (r2.x + r2.y + r3.x + r3.y) * 0.5f;
    LH1.x = (r2.x + r2.y - r3.x - r3.y) * 0.5f;
    HL1.x = (r2.x - r2.y + r3.x - r3.y) * 0.5f;
    HH1.x = (r2.x - r2.y - r3.x + r3.y) * 0.5f;
    LL1.y = (r2.z + r2.w + r3.z + r3.w) * 0.5f;
    LH1.y = (r2.z + r2.w - r3.z - r3.w) * 0.5f;
    HL1.y = (r2.z - r2.w + r3.z - r3.w) * 0.5f;
    HH1.y = (r2.z - r2.w - r3.z + r3.w) * 0.5f;

    // Output: [B, 4, C, H2, W2]
    const unsigned plane   = H2 * W2;                      // 65536
    const unsigned sstride = C_ * plane;                   // 2,097,152
    const unsigned obase   = (b * 4u * C_ + c) * plane
                             + (2u * hq) * W2 + 2u * wpair;

    *reinterpret_cast<float2*>(out + obase)                      = LL0;
    *reinterpret_cast<float2*>(out + obase + W2)                 = LL1;
    *reinterpret_cast<float2*>(out + obase + sstride)            = LH0;
    *reinterpret_cast<float2*>(out + obase + sstride + W2)       = LH1;
    *reinterpret_cast<float2*>(out + obase + 2u * sstride)       = HL0;
    *reinterpret_cast<float2*>(out + obase + 2u * sstride + W2)  = HL1;
    *reinterpret_cast<float2*>(out + obase + 3u * sstride)       = HH0;
    *reinterpret_cast<float2*>(out + obase + 3u * sstride + W2)  = HH1;
}

extern "C" void kernel_launch(void* const* d_in, const int* in_sizes, int n_in,
                              void* d_out, int out_size)
{
    const float* in = (const float*)d_in[0];
    float* out = (float*)d_out;

    const int total_threads = B_ * C_ * (H2/2) * (W2/2);   // 4,194,304
    const int threads = 256;
    const int blocks  = total_threads / threads;           // 16,384

    haar_dwt2_kernel<<<blocks, threads>>>(in, out);
}